// round 2
// baseline (speedup 1.0000x reference)
#include <cuda_runtime.h>
#include <math.h>

// Problem dims
constexpr int kB   = 1024;   // batch
constexpr int kT   = 256;    // block size (sequence)
constexpr int kC   = 384;    // n_embed
constexpr int kH   = 64;     // head size
constexpr int kN   = 192;    // packed q|k|v width
constexpr long kM  = (long)kB * kT;  // 262144 rows

// Scratch (device globals: allocation-free rule)
__device__ float g_w[kC * kN];                 // packed tf32 weights, q pre-scaled
__device__ float g_qkv[(size_t)kM * kN];       // tf32-rounded q,k,v  (~201MB)

// ---------------- helpers ----------------
__device__ __forceinline__ float ftf32(float f) {
    unsigned u;
    asm("cvt.rna.tf32.f32 %0, %1;" : "=r"(u) : "f"(f));
    return __uint_as_float(u);
}

// D += A*B,  m16n8k8 tf32, A row-major, B col-major, fp32 accum
__device__ __forceinline__ void mma_tf32(float* d, const unsigned* a, const unsigned* b) {
    asm volatile(
        "mma.sync.aligned.m16n8k8.row.col.f32.tf32.tf32.f32 "
        "{%0,%1,%2,%3}, {%4,%5,%6,%7}, {%8,%9}, {%0,%1,%2,%3};\n"
        : "+f"(d[0]), "+f"(d[1]), "+f"(d[2]), "+f"(d[3])
        : "r"(a[0]), "r"(a[1]), "r"(a[2]), "r"(a[3]),
          "r"(b[0]), "r"(b[1]));
}

// ---------------- kernel 0: pack weights ----------------
__global__ void pack_w_kernel(const float* __restrict__ Wq,
                              const float* __restrict__ Wk,
                              const float* __restrict__ Wv) {
    int i = blockIdx.x * blockDim.x + threadIdx.x;
    if (i >= kC * kH) return;
    int r = i / kH, c = i % kH;
    const float scale = rsqrtf((float)kC);  // C**-0.5 folded into Wq
    g_w[r * kN + c]        = ftf32(Wq[i] * scale);
    g_w[r * kN + 64 + c]   = ftf32(Wk[i]);
    g_w[r * kN + 128 + c]  = ftf32(Wv[i]);
}

// ---------------- kernel 1: QKV projection GEMM ----------------
// [262144 x 384] @ [384 x 192] -> g_qkv. Block tile 64x192, 8 warps (2M x 4N),
// warp tile 32x48, K-step 16 (2 tf32 mma k-steps).
__global__ __launch_bounds__(256) void qkv_gemm_kernel(const float* __restrict__ x) {
    __shared__ float As[64][20];    // padded: conflict-free a-frag LDS
    __shared__ float Bs[16][200];   // padded: conflict-free b-frag LDS

    const int tid  = threadIdx.x;
    const int lane = tid & 31, warp = tid >> 5;
    const int wm = warp >> 2, wn = warp & 3;  // 2 x 4
    const int g = lane >> 2, t = lane & 3;
    const long m0 = (long)blockIdx.x * 64;

    float acc[2][6][4];
    #pragma unroll
    for (int mt = 0; mt < 2; mt++)
        #pragma unroll
        for (int nt = 0; nt < 6; nt++)
            #pragma unroll
            for (int j = 0; j < 4; j++) acc[mt][nt][j] = 0.f;

    const int arow = tid >> 2;          // 0..63
    const int acq  = (tid & 3) * 4;     // 0,4,8,12

    for (int kt = 0; kt < kC; kt += 16) {
        // A tile 64x16 (x, cvt to tf32)
        float4 av = *(const float4*)(x + (m0 + arow) * kC + kt + acq);
        av.x = ftf32(av.x); av.y = ftf32(av.y); av.z = ftf32(av.z); av.w = ftf32(av.w);
        *(float4*)&As[arow][acq] = av;
        // B tile 16x192 (already tf32)
        #pragma unroll
        for (int j = 0; j < 3; j++) {
            int idx = tid + j * 256;
            int br = idx / 48, bq = (idx % 48) * 4;
            *(float4*)&Bs[br][bq] = *(const float4*)(g_w + (kt + br) * kN + bq);
        }
        __syncthreads();

        #pragma unroll
        for (int ks = 0; ks < 16; ks += 8) {
            unsigned a[2][4];
            #pragma unroll
            for (int mt = 0; mt < 2; mt++) {
                int rb = wm * 32 + mt * 16;
                a[mt][0] = __float_as_uint(As[rb + g    ][ks + t    ]);
                a[mt][1] = __float_as_uint(As[rb + g + 8][ks + t    ]);
                a[mt][2] = __float_as_uint(As[rb + g    ][ks + t + 4]);
                a[mt][3] = __float_as_uint(As[rb + g + 8][ks + t + 4]);
            }
            #pragma unroll
            for (int nt = 0; nt < 6; nt++) {
                int col = wn * 48 + nt * 8 + g;
                unsigned bb[2] = { __float_as_uint(Bs[ks + t    ][col]),
                                   __float_as_uint(Bs[ks + t + 4][col]) };
                #pragma unroll
                for (int mt = 0; mt < 2; mt++) mma_tf32(acc[mt][nt], a[mt], bb);
            }
        }
        __syncthreads();
    }

    // Epilogue: tf32-round outputs (consumed as tf32 operands downstream)
    #pragma unroll
    for (int mt = 0; mt < 2; mt++) {
        long r0 = m0 + wm * 32 + mt * 16 + g;
        #pragma unroll
        for (int nt = 0; nt < 6; nt++) {
            int cb = wn * 48 + nt * 8 + 2 * t;
            float2 v0 = { ftf32(acc[mt][nt][0]), ftf32(acc[mt][nt][1]) };
            float2 v1 = { ftf32(acc[mt][nt][2]), ftf32(acc[mt][nt][3]) };
            *(float2*)(g_qkv + r0 * kN + cb)       = v0;
            *(float2*)(g_qkv + (r0 + 8) * kN + cb) = v1;
        }
    }
}

// ---------------- kernel 2: fused causal attention ----------------
// One block per (query-tile qt in [0,4), batch b). 256 threads = 8 warps.
// smem: K[256][68], V[256][72], Q[64][68] (reused as P[64][260]), reduce bufs.
constexpr int KS_OFF = 0;                 // 256*68 = 17408
constexpr int VS_OFF = 17408;             // 256*72 = 18432
constexpr int QP_OFF = 35840;             // max(64*68, 64*260) = 16640
constexpr int RM_OFF = 52480;             // 64*4
constexpr int RL_OFF = 52736;             // 64*4
constexpr int SMEM_FLOATS = 52992;        // 211,968 bytes

__global__ __launch_bounds__(256, 1) void attn_kernel(float* __restrict__ out) {
    extern __shared__ float sm[];
    float* Ks = sm + KS_OFF;
    float* Vs = sm + VS_OFF;
    float* Qs = sm + QP_OFF;
    float* Ps = sm + QP_OFF;   // reuses Q region after S is computed
    float* RM = sm + RM_OFF;
    float* RL = sm + RL_OFF;

    const int tid  = threadIdx.x;
    const int lane = tid & 31, warp = tid >> 5;
    const int wm = warp >> 2, wn = warp & 3;   // 2(M) x 4(N)
    const int g = lane >> 2, t = lane & 3;
    const int qt = blockIdx.x;
    const long rowbase = (long)blockIdx.y * kT;

    // Stage K, V (full 256x64) and Q tile (64x64)
    for (int i = tid; i < 256 * 16; i += 256) {
        int r = i >> 4, q = (i & 15) * 4;
        *(float4*)(Ks + r * 68 + q) = *(const float4*)(g_qkv + (rowbase + r) * kN + 64 + q);
        *(float4*)(Vs + r * 72 + q) = *(const float4*)(g_qkv + (rowbase + r) * kN + 128 + q);
    }
    for (int i = tid; i < 64 * 16; i += 256) {
        int r = i >> 4, q = (i & 15) * 4;
        *(float4*)(Qs + r * 68 + q) = *(const float4*)(g_qkv + (rowbase + qt * 64 + r) * kN + q);
    }
    __syncthreads();

    // S = Q K^T : warp tile 32(q) x 64(k); 2 mtiles x 8 ntiles
    float s[2][8][4];
    #pragma unroll
    for (int mt = 0; mt < 2; mt++)
        #pragma unroll
        for (int nt = 0; nt < 8; nt++)
            #pragma unroll
            for (int j = 0; j < 4; j++) s[mt][nt][j] = 0.f;

    #pragma unroll
    for (int ks = 0; ks < 64; ks += 8) {
        unsigned a[2][4];
        #pragma unroll
        for (int mt = 0; mt < 2; mt++) {
            int rb = wm * 32 + mt * 16;
            a[mt][0] = __float_as_uint(Qs[(rb + g    ) * 68 + ks + t    ]);
            a[mt][1] = __float_as_uint(Qs[(rb + g + 8) * 68 + ks + t    ]);
            a[mt][2] = __float_as_uint(Qs[(rb + g    ) * 68 + ks + t + 4]);
            a[mt][3] = __float_as_uint(Qs[(rb + g + 8) * 68 + ks + t + 4]);
        }
        #pragma unroll
        for (int nt = 0; nt < 8; nt++) {
            int key = wn * 64 + nt * 8 + g;
            unsigned bb[2] = { __float_as_uint(Ks[key * 68 + ks + t    ]),
                               __float_as_uint(Ks[key * 68 + ks + t + 4]) };
            #pragma unroll
            for (int mt = 0; mt < 2; mt++) mma_tf32(s[mt][nt], a[mt], bb);
        }
    }

    // Causal mask + per-row max (quad shuffle, then cross-warp via smem)
    #pragma unroll
    for (int mt = 0; mt < 2; mt++)
        #pragma unroll
        for (int h = 0; h < 2; h++) {
            int ql = wm * 32 + mt * 16 + g + 8 * h;
            int qglob = qt * 64 + ql;
            float mm = -1e30f;
            #pragma unroll
            for (int nt = 0; nt < 8; nt++) {
                int k0 = wn * 64 + nt * 8 + 2 * t;
                float v0 = (k0     <= qglob) ? s[mt][nt][2 * h    ] : -1e30f;
                float v1 = (k0 + 1 <= qglob) ? s[mt][nt][2 * h + 1] : -1e30f;
                s[mt][nt][2 * h]     = v0;
                s[mt][nt][2 * h + 1] = v1;
                mm = fmaxf(mm, fmaxf(v0, v1));
            }
            mm = fmaxf(mm, __shfl_xor_sync(0xffffffffu, mm, 1));
            mm = fmaxf(mm, __shfl_xor_sync(0xffffffffu, mm, 2));
            if (t == 0) RM[ql * 4 + wn] = mm;
        }
    __syncthreads();

    // exp + per-row sum
    #pragma unroll
    for (int mt = 0; mt < 2; mt++)
        #pragma unroll
        for (int h = 0; h < 2; h++) {
            int ql = wm * 32 + mt * 16 + g + 8 * h;
            float mf = fmaxf(fmaxf(RM[ql * 4 + 0], RM[ql * 4 + 1]),
                             fmaxf(RM[ql * 4 + 2], RM[ql * 4 + 3]));
            float ss = 0.f;
            #pragma unroll
            for (int nt = 0; nt < 8; nt++) {
                float p0 = __expf(s[mt][nt][2 * h]     - mf);
                float p1 = __expf(s[mt][nt][2 * h + 1] - mf);
                s[mt][nt][2 * h]     = p0;
                s[mt][nt][2 * h + 1] = p1;
                ss += p0 + p1;
            }
            ss += __shfl_xor_sync(0xffffffffu, ss, 1);
            ss += __shfl_xor_sync(0xffffffffu, ss, 2);
            if (t == 0) RL[ql * 4 + wn] = ss;
        }
    __syncthreads();

    // normalize, tf32-round, write P to smem (A-operand layout)
    #pragma unroll
    for (int mt = 0; mt < 2; mt++)
        #pragma unroll
        for (int h = 0; h < 2; h++) {
            int ql = wm * 32 + mt * 16 + g + 8 * h;
            float li = RL[ql * 4 + 0] + RL[ql * 4 + 1] + RL[ql * 4 + 2] + RL[ql * 4 + 3];
            float rinv = 1.0f / li;
            #pragma unroll
            for (int nt = 0; nt < 8; nt++) {
                int k0 = wn * 64 + nt * 8 + 2 * t;
                float2 pv = { ftf32(s[mt][nt][2 * h] * rinv),
                              ftf32(s[mt][nt][2 * h + 1] * rinv) };
                *(float2*)(Ps + ql * 260 + k0) = pv;
            }
        }
    __syncthreads();

    // O = P @ V : warp tile 32(q) x 16(h); K-dim = 256 keys
    float o[2][2][4];
    #pragma unroll
    for (int mt = 0; mt < 2; mt++)
        #pragma unroll
        for (int nt = 0; nt < 2; nt++)
            #pragma unroll
            for (int j = 0; j < 4; j++) o[mt][nt][j] = 0.f;

    #pragma unroll 4
    for (int ks = 0; ks < 256; ks += 8) {
        unsigned a[2][4];
        #pragma unroll
        for (int mt = 0; mt < 2; mt++) {
            int rb = wm * 32 + mt * 16;
            a[mt][0] = __float_as_uint(Ps[(rb + g    ) * 260 + ks + t    ]);
            a[mt][1] = __float_as_uint(Ps[(rb + g + 8) * 260 + ks + t    ]);
            a[mt][2] = __float_as_uint(Ps[(rb + g    ) * 260 + ks + t + 4]);
            a[mt][3] = __float_as_uint(Ps[(rb + g + 8) * 260 + ks + t + 4]);
        }
        #pragma unroll
        for (int nt = 0; nt < 2; nt++) {
            int col = wn * 16 + nt * 8 + g;
            unsigned bb[2] = { __float_as_uint(Vs[(ks + t    ) * 72 + col]),
                               __float_as_uint(Vs[(ks + t + 4) * 72 + col]) };
            #pragma unroll
            for (int mt = 0; mt < 2; mt++) mma_tf32(o[mt][nt], a[mt], bb);
        }
    }

    // Epilogue -> out [B*T, 64] fp32
    #pragma unroll
    for (int mt = 0; mt < 2; mt++) {
        long r0 = rowbase + qt * 64 + wm * 32 + mt * 16 + g;
        #pragma unroll
        for (int nt = 0; nt < 2; nt++) {
            int cb = wn * 16 + nt * 8 + 2 * t;
            float2 v0 = { o[mt][nt][0], o[mt][nt][1] };
            float2 v1 = { o[mt][nt][2], o[mt][nt][3] };
            *(float2*)(out + r0 * kH + cb)       = v0;
            *(float2*)(out + (r0 + 8) * kH + cb) = v1;
        }
    }
}

// ---------------- host launcher ----------------
extern "C" void kernel_launch(void* const* d_in, const int* in_sizes, int n_in,
                              void* d_out, int out_size) {
    const float* x  = (const float*)d_in[0];
    const float* Wq = (const float*)d_in[1];
    const float* Wk = (const float*)d_in[2];
    const float* Wv = (const float*)d_in[3];
    float* out = (float*)d_out;

    pack_w_kernel<<<(kC * kH + 255) / 256, 256>>>(Wq, Wk, Wv);
    qkv_gemm_kernel<<<(int)(kM / 64), 256>>>(x);

    cudaFuncSetAttribute(attn_kernel, cudaFuncAttributeMaxDynamicSharedMemorySize,
                         SMEM_FLOATS * (int)sizeof(float));
    attn_kernel<<<dim3(4, kB), 256, SMEM_FLOATS * sizeof(float)>>>(out);
}

// round 3
// speedup vs baseline: 1.6461x; 1.6461x over previous
#include <cuda_runtime.h>
#include <math.h>

// Problem dims
constexpr int kB   = 1024;   // batch
constexpr int kT   = 256;    // block size (sequence)
constexpr int kC   = 384;    // n_embed
constexpr int kH   = 64;     // head size
constexpr int kN   = 192;    // packed q|k|v width
constexpr long kM  = (long)kB * kT;  // 262144 rows

// Scratch (device globals: allocation-free rule)
__device__ float g_w[kC * kN];                 // packed tf32 weights, q pre-scaled
__device__ float g_qkv[(size_t)kM * kN];       // tf32-rounded q,k,v  (~201MB)

// ---------------- helpers ----------------
__device__ __forceinline__ float ftf32(float f) {
    unsigned u;
    asm("cvt.rna.tf32.f32 %0, %1;" : "=r"(u) : "f"(f));
    return __uint_as_float(u);
}

// D += A*B,  m16n8k8 tf32, A row-major, B col-major, fp32 accum
__device__ __forceinline__ void mma_tf32(float* d, const unsigned* a, const unsigned* b) {
    asm volatile(
        "mma.sync.aligned.m16n8k8.row.col.f32.tf32.tf32.f32 "
        "{%0,%1,%2,%3}, {%4,%5,%6,%7}, {%8,%9}, {%0,%1,%2,%3};\n"
        : "+f"(d[0]), "+f"(d[1]), "+f"(d[2]), "+f"(d[3])
        : "r"(a[0]), "r"(a[1]), "r"(a[2]), "r"(a[3]),
          "r"(b[0]), "r"(b[1]));
}

__device__ __forceinline__ void cp16(void* s, const void* g) {
    unsigned sa = (unsigned)__cvta_generic_to_shared(s);
    asm volatile("cp.async.cg.shared.global [%0], [%1], 16;\n" :: "r"(sa), "l"(g));
}
#define CP_COMMIT()  asm volatile("cp.async.commit_group;\n")
#define CP_WAIT(n)   asm volatile("cp.async.wait_group %0;\n" :: "n"(n))

// ---------------- kernel 0: pack weights ----------------
__global__ void pack_w_kernel(const float* __restrict__ Wq,
                              const float* __restrict__ Wk,
                              const float* __restrict__ Wv) {
    int i = blockIdx.x * blockDim.x + threadIdx.x;
    if (i >= kC * kH) return;
    int r = i / kH, c = i % kH;
    const float scale = rsqrtf((float)kC);  // C**-0.5 folded into Wq
    g_w[r * kN + c]        = ftf32(Wq[i] * scale);
    g_w[r * kN + 64 + c]   = ftf32(Wk[i]);
    g_w[r * kN + 128 + c]  = ftf32(Wv[i]);
}

// ---------------- kernel 1: QKV projection GEMM ----------------
// [262144 x 384] @ [384 x 192] -> g_qkv. Block tile 64x192, 8 warps (2M x 4N),
// warp tile 32x48. cp.async double-buffered over 24 k-tiles of 16.
__global__ __launch_bounds__(256) void qkv_gemm_kernel(const float* __restrict__ x) {
    __shared__ float As[2][64][20];    // raw fp32 x (cvt at frag load)
    __shared__ float Bs[2][16][200];   // tf32 weights

    const int tid  = threadIdx.x;
    const int lane = tid & 31, warp = tid >> 5;
    const int wm = warp >> 2, wn = warp & 3;  // 2 x 4
    const int g = lane >> 2, t = lane & 3;
    const long m0 = (long)blockIdx.x * 64;

    const int arow = tid >> 2;          // 0..63
    const int acq  = (tid & 3) * 4;     // 0,4,8,12

    float acc[2][6][4];
    #pragma unroll
    for (int mt = 0; mt < 2; mt++)
        #pragma unroll
        for (int nt = 0; nt < 6; nt++)
            #pragma unroll
            for (int j = 0; j < 4; j++) acc[mt][nt][j] = 0.f;

    auto load_tile = [&](int kt, int buf) {
        cp16(&As[buf][arow][acq], x + (m0 + arow) * kC + kt * 16 + acq);
        #pragma unroll
        for (int j = 0; j < 3; j++) {
            int idx = tid + j * 256;
            int br = idx / 48, bq = (idx % 48) * 4;
            cp16(&Bs[buf][br][bq], g_w + (kt * 16 + br) * kN + bq);
        }
        CP_COMMIT();
    };

    load_tile(0, 0);

    constexpr int NKT = kC / 16;  // 24
    for (int kt = 0; kt < NKT; kt++) {
        if (kt + 1 < NKT) {
            load_tile(kt + 1, (kt + 1) & 1);
            CP_WAIT(1);
        } else {
            CP_WAIT(0);
        }
        __syncthreads();

        int buf = kt & 1;
        #pragma unroll
        for (int ks = 0; ks < 16; ks += 8) {
            unsigned a[2][4];
            #pragma unroll
            for (int mt = 0; mt < 2; mt++) {
                int rb = wm * 32 + mt * 16;
                a[mt][0] = __float_as_uint(ftf32(As[buf][rb + g    ][ks + t    ]));
                a[mt][1] = __float_as_uint(ftf32(As[buf][rb + g + 8][ks + t    ]));
                a[mt][2] = __float_as_uint(ftf32(As[buf][rb + g    ][ks + t + 4]));
                a[mt][3] = __float_as_uint(ftf32(As[buf][rb + g + 8][ks + t + 4]));
            }
            #pragma unroll
            for (int nt = 0; nt < 6; nt++) {
                int col = wn * 48 + nt * 8 + g;
                unsigned bb[2] = { __float_as_uint(Bs[buf][ks + t    ][col]),
                                   __float_as_uint(Bs[buf][ks + t + 4][col]) };
                #pragma unroll
                for (int mt = 0; mt < 2; mt++) mma_tf32(acc[mt][nt], a[mt], bb);
            }
        }
        __syncthreads();
    }

    // Epilogue: tf32-round outputs (consumed as tf32 operands downstream)
    #pragma unroll
    for (int mt = 0; mt < 2; mt++) {
        long r0 = m0 + wm * 32 + mt * 16 + g;
        #pragma unroll
        for (int nt = 0; nt < 6; nt++) {
            int cb = wn * 48 + nt * 8 + 2 * t;
            float2 v0 = { ftf32(acc[mt][nt][0]), ftf32(acc[mt][nt][1]) };
            float2 v1 = { ftf32(acc[mt][nt][2]), ftf32(acc[mt][nt][3]) };
            *(float2*)(g_qkv + r0 * kN + cb)       = v0;
            *(float2*)(g_qkv + (r0 + 8) * kN + cb) = v1;
        }
    }
}

// ---------------- kernel 2: fused causal attention ----------------
// 512 threads = 16 warps, layout 4(M) x 4(N). Templated on query tile QT so
// the causal key range L=(QT+1)*64 is compile-time; key column tiles are
// round-robin across wn so all warps stay busy for every QT.
constexpr int ATTN_SMEM_BYTES = (256*68 + 256*72 + 64*260 + 512) * 4;  // 211,968

template<int QT>
__device__ __forceinline__ void attn_body(float* __restrict__ out, float* sm) {
    constexpr int L   = (QT + 1) * 64;   // causal key range
    constexpr int NTW = L / 32;          // 8-wide n-tiles per warp: 2,4,6,8
    constexpr int PST = L + 4;           // P row stride (== 4 mod 32)

    float* Ks  = sm;                     // [L][68]
    float* Vs  = sm + L * 68;            // [L][72]
    float* QPs = sm + L * 68 + L * 72;   // Q [64][68], then P [64][PST]
    float* RM  = QPs + 64 * PST;
    float* RL  = RM + 256;

    const int tid  = threadIdx.x;
    const int lane = tid & 31, warp = tid >> 5;
    const int wm = warp >> 2, wn = warp & 3;   // 4(M) x 4(N)
    const int g = lane >> 2, t = lane & 3;
    const long rowbase = (long)blockIdx.y * kT;

    // Stage K,V rows [0,L) and the 64-row Q tile
    for (int i = tid; i < L * 16; i += 512) {
        int r = i >> 4, q = (i & 15) * 4;
        *(float4*)(Ks + r * 68 + q) = *(const float4*)(g_qkv + (rowbase + r) * kN + 64 + q);
        *(float4*)(Vs + r * 72 + q) = *(const float4*)(g_qkv + (rowbase + r) * kN + 128 + q);
    }
    for (int i = tid; i < 64 * 16; i += 512) {
        int r = i >> 4, q = (i & 15) * 4;
        *(float4*)(QPs + r * 68 + q) =
            *(const float4*)(g_qkv + (rowbase + QT * 64 + r) * kN + q);
    }
    __syncthreads();

    // S = Q K^T : warp m-tile 16 rows, n-tiles jj = wn + 4*i (round-robin)
    float s[NTW][4] = {};
    #pragma unroll
    for (int ks = 0; ks < 64; ks += 8) {
        const int rb = wm * 16;
        unsigned a[4] = {
            __float_as_uint(QPs[(rb + g    ) * 68 + ks + t    ]),
            __float_as_uint(QPs[(rb + g + 8) * 68 + ks + t    ]),
            __float_as_uint(QPs[(rb + g    ) * 68 + ks + t + 4]),
            __float_as_uint(QPs[(rb + g + 8) * 68 + ks + t + 4]) };
        #pragma unroll
        for (int i = 0; i < NTW; i++) {
            int col = (wn + 4 * i) * 8 + g;
            unsigned bb[2] = { __float_as_uint(Ks[col * 68 + ks + t    ]),
                               __float_as_uint(Ks[col * 68 + ks + t + 4]) };
            mma_tf32(s[i], a, bb);
        }
    }

    // Causal mask + row max (quad shuffle, then cross-warp via smem)
    #pragma unroll
    for (int h = 0; h < 2; h++) {
        int row = wm * 16 + g + 8 * h;
        int qglob = QT * 64 + row;
        float mm = -1e30f;
        #pragma unroll
        for (int i = 0; i < NTW; i++) {
            int k0 = (wn + 4 * i) * 8 + 2 * t;
            float v0 = (k0     <= qglob) ? s[i][2 * h    ] : -1e30f;
            float v1 = (k0 + 1 <= qglob) ? s[i][2 * h + 1] : -1e30f;
            s[i][2 * h]     = v0;
            s[i][2 * h + 1] = v1;
            mm = fmaxf(mm, fmaxf(v0, v1));
        }
        mm = fmaxf(mm, __shfl_xor_sync(0xffffffffu, mm, 1));
        mm = fmaxf(mm, __shfl_xor_sync(0xffffffffu, mm, 2));
        if (t == 0) RM[row * 4 + wn] = mm;
    }
    __syncthreads();

    // exp + row sum
    #pragma unroll
    for (int h = 0; h < 2; h++) {
        int row = wm * 16 + g + 8 * h;
        float mf = fmaxf(fmaxf(RM[row * 4 + 0], RM[row * 4 + 1]),
                         fmaxf(RM[row * 4 + 2], RM[row * 4 + 3]));
        float ss = 0.f;
        #pragma unroll
        for (int i = 0; i < NTW; i++) {
            float p0 = __expf(s[i][2 * h]     - mf);
            float p1 = __expf(s[i][2 * h + 1] - mf);
            s[i][2 * h]     = p0;
            s[i][2 * h + 1] = p1;
            ss += p0 + p1;
        }
        ss += __shfl_xor_sync(0xffffffffu, ss, 1);
        ss += __shfl_xor_sync(0xffffffffu, ss, 2);
        if (t == 0) RL[row * 4 + wn] = ss;
    }
    __syncthreads();

    // normalize, tf32-round, write P (A-operand layout) into the Q region
    #pragma unroll
    for (int h = 0; h < 2; h++) {
        int row = wm * 16 + g + 8 * h;
        float li = RL[row * 4 + 0] + RL[row * 4 + 1] + RL[row * 4 + 2] + RL[row * 4 + 3];
        float rinv = 1.0f / li;
        #pragma unroll
        for (int i = 0; i < NTW; i++) {
            int k0 = (wn + 4 * i) * 8 + 2 * t;
            float2 pv = { ftf32(s[i][2 * h] * rinv),
                          ftf32(s[i][2 * h + 1] * rinv) };
            *(float2*)(QPs + row * PST + k0) = pv;
        }
    }
    __syncthreads();

    // O = P @ V : warp tile 16(q) x 16(h), K-dim = L keys
    float o[2][4] = {};
    #pragma unroll 4
    for (int ks = 0; ks < L; ks += 8) {
        const int rb = wm * 16;
        unsigned a[4] = {
            __float_as_uint(QPs[(rb + g    ) * PST + ks + t    ]),
            __float_as_uint(QPs[(rb + g + 8) * PST + ks + t    ]),
            __float_as_uint(QPs[(rb + g    ) * PST + ks + t + 4]),
            __float_as_uint(QPs[(rb + g + 8) * PST + ks + t + 4]) };
        #pragma unroll
        for (int nt = 0; nt < 2; nt++) {
            int col = wn * 16 + nt * 8 + g;
            unsigned bb[2] = { __float_as_uint(Vs[(ks + t    ) * 72 + col]),
                               __float_as_uint(Vs[(ks + t + 4) * 72 + col]) };
            mma_tf32(o[nt], a, bb);
        }
    }

    // Epilogue -> out [B*T, 64] fp32
    long r0 = rowbase + QT * 64 + wm * 16 + g;
    #pragma unroll
    for (int nt = 0; nt < 2; nt++) {
        int cb = wn * 16 + nt * 8 + 2 * t;
        float2 v0 = { o[nt][0], o[nt][1] };
        float2 v1 = { o[nt][2], o[nt][3] };
        *(float2*)(out + r0 * kH + cb)       = v0;
        *(float2*)(out + (r0 + 8) * kH + cb) = v1;
    }
}

__global__ __launch_bounds__(512, 1) void attn_kernel(float* __restrict__ out) {
    extern __shared__ float sm[];
    switch (blockIdx.x) {
        case 0: attn_body<0>(out, sm); break;
        case 1: attn_body<1>(out, sm); break;
        case 2: attn_body<2>(out, sm); break;
        default: attn_body<3>(out, sm); break;
    }
}

// ---------------- host launcher ----------------
extern "C" void kernel_launch(void* const* d_in, const int* in_sizes, int n_in,
                              void* d_out, int out_size) {
    const float* x  = (const float*)d_in[0];
    const float* Wq = (const float*)d_in[1];
    const float* Wk = (const float*)d_in[2];
    const float* Wv = (const float*)d_in[3];
    float* out = (float*)d_out;

    pack_w_kernel<<<(kC * kH + 255) / 256, 256>>>(Wq, Wk, Wv);
    qkv_gemm_kernel<<<(int)(kM / 64), 256>>>(x);

    cudaFuncSetAttribute(attn_kernel, cudaFuncAttributeMaxDynamicSharedMemorySize,
                         ATTN_SMEM_BYTES);
    attn_kernel<<<dim3(4, kB), 512, ATTN_SMEM_BYTES>>>(out);
}

// round 4
// speedup vs baseline: 2.0860x; 1.2672x over previous
#include <cuda_runtime.h>
#include <math.h>

// Problem dims
constexpr int kB   = 1024;   // batch
constexpr int kT   = 256;    // block size (sequence)
constexpr int kC   = 384;    // n_embed
constexpr int kH   = 64;     // head size
constexpr int kN   = 192;    // packed q|k|v width

// Packed tf32 weights (q pre-scaled by C^-0.5)
__device__ float g_w[kC * kN];

// ---------------- helpers ----------------
__device__ __forceinline__ float ftf32(float f) {
    unsigned u;
    asm("cvt.rna.tf32.f32 %0, %1;" : "=r"(u) : "f"(f));
    return __uint_as_float(u);
}

// D += A*B,  m16n8k8 tf32, A row-major, B col-major, fp32 accum
__device__ __forceinline__ void mma_tf32(float* d, const unsigned* a, const unsigned* b) {
    asm volatile(
        "mma.sync.aligned.m16n8k8.row.col.f32.tf32.tf32.f32 "
        "{%0,%1,%2,%3}, {%4,%5,%6,%7}, {%8,%9}, {%0,%1,%2,%3};\n"
        : "+f"(d[0]), "+f"(d[1]), "+f"(d[2]), "+f"(d[3])
        : "r"(a[0]), "r"(a[1]), "r"(a[2]), "r"(a[3]),
          "r"(b[0]), "r"(b[1]));
}

__device__ __forceinline__ void cp16(void* s, const void* g) {
    unsigned sa = (unsigned)__cvta_generic_to_shared(s);
    asm volatile("cp.async.cg.shared.global [%0], [%1], 16;\n" :: "r"(sa), "l"(g));
}
#define CP_COMMIT()  asm volatile("cp.async.commit_group;\n")
#define CP_WAIT(n)   asm volatile("cp.async.wait_group %0;\n" :: "n"(n))

// ---------------- kernel 0: pack weights ----------------
__global__ void pack_w_kernel(const float* __restrict__ Wq,
                              const float* __restrict__ Wk,
                              const float* __restrict__ Wv) {
    int i = blockIdx.x * blockDim.x + threadIdx.x;
    if (i >= kC * kH) return;
    int r = i / kH, c = i % kH;
    const float scale = rsqrtf((float)kC);  // C**-0.5 folded into Wq
    g_w[r * kN + c]        = ftf32(Wq[i] * scale);
    g_w[r * kN + 64 + c]   = ftf32(Wk[i]);
    g_w[r * kN + 128 + c]  = ftf32(Wv[i]);
}

// ---------------- fused kernel: one CTA per batch ----------------
// smem (floats): Ks[256][68] @0, Vs[256][72] @17408, Qs[256][68] @35840,
//                RM @53248 (256), RL @53504 (256)  -> 53760 floats = 215,040 B
// Projection streaming buffers ALIAS rows 128..255 of Ks/Vs:
//   xb = Ks + 128*68  : 2 x [128][20]  (5120 fl, capacity 8704)
//   Wb = Vs + 128*72  : 2 x [16][200]  (6400 fl, capacity 9216)
// Pass 0 projects rows 0..127 (epilogue never touches buffer area);
// pass 1 projects rows 128..255 (epilogue runs after the final loop barrier,
// when the buffers are dead).
constexpr int SMEM_FLOATS = 53760;

__global__ __launch_bounds__(512, 1) void fused_kernel(const float* __restrict__ x,
                                                       float* __restrict__ out) {
    extern __shared__ float sm[];
    float* Ks = sm;
    float* Vs = sm + 17408;
    float* Qs = sm + 35840;
    float* RM = sm + 53248;
    float* RL = sm + 53504;
    float* xb = Ks + 128 * 68;   // [2][128][20]
    float* Wb = Vs + 128 * 72;   // [2][16][200]

    const int tid  = threadIdx.x;
    const int lane = tid & 31, warp = tid >> 5;
    const int wm = warp >> 2, wn = warp & 3;   // 4(M) x 4(N)
    const int g = lane >> 2, t = lane & 3;
    const long bbase = (long)blockIdx.x * kT;

    // ================= QKV projection: two 128-row passes =================
    #pragma unroll 1
    for (int pass = 0; pass < 2; pass++) {
        const int m0 = pass * 128;
        float acc[2][6][4];
        #pragma unroll
        for (int mt = 0; mt < 2; mt++)
            #pragma unroll
            for (int nt = 0; nt < 6; nt++)
                #pragma unroll
                for (int j = 0; j < 4; j++) acc[mt][nt][j] = 0.f;

        auto load_tile = [&](int kt, int buf) {
            // x tile: 128 x 16 fp32 = 512 float4, one per thread
            {
                int r = tid >> 2, c4 = (tid & 3) * 4;
                cp16(xb + buf * 2560 + r * 20 + c4,
                     x + (bbase + m0 + r) * kC + kt * 16 + c4);
            }
            // W tile: 16 x 192 = 768 float4
            {
                int br = tid / 48, bq = (tid % 48) * 4;
                cp16(Wb + buf * 3200 + br * 200 + bq,
                     g_w + (kt * 16 + br) * kN + bq);
                if (tid < 256) {
                    int idx = tid + 512;
                    int br2 = idx / 48, bq2 = (idx % 48) * 4;
                    cp16(Wb + buf * 3200 + br2 * 200 + bq2,
                         g_w + (kt * 16 + br2) * kN + bq2);
                }
            }
            CP_COMMIT();
        };

        load_tile(0, 0);
        constexpr int NKT = kC / 16;  // 24
        for (int kt = 0; kt < NKT; kt++) {
            if (kt + 1 < NKT) { load_tile(kt + 1, (kt + 1) & 1); CP_WAIT(1); }
            else              { CP_WAIT(0); }
            __syncthreads();

            const float* Ax = xb + (kt & 1) * 2560;
            const float* Bx = Wb + (kt & 1) * 3200;
            #pragma unroll
            for (int ks = 0; ks < 16; ks += 8) {
                unsigned a[2][4];
                #pragma unroll
                for (int mt = 0; mt < 2; mt++) {
                    int rb = wm * 32 + mt * 16;
                    a[mt][0] = __float_as_uint(ftf32(Ax[(rb + g    ) * 20 + ks + t    ]));
                    a[mt][1] = __float_as_uint(ftf32(Ax[(rb + g + 8) * 20 + ks + t    ]));
                    a[mt][2] = __float_as_uint(ftf32(Ax[(rb + g    ) * 20 + ks + t + 4]));
                    a[mt][3] = __float_as_uint(ftf32(Ax[(rb + g + 8) * 20 + ks + t + 4]));
                }
                #pragma unroll
                for (int nt = 0; nt < 6; nt++) {
                    int col = wn * 48 + nt * 8 + g;
                    unsigned bb[2] = { __float_as_uint(Bx[(ks + t    ) * 200 + col]),
                                       __float_as_uint(Bx[(ks + t + 4) * 200 + col]) };
                    #pragma unroll
                    for (int mt = 0; mt < 2; mt++) mma_tf32(acc[mt][nt], a[mt], bb);
                }
            }
            __syncthreads();  // final iter: buffers dead after this barrier
        }

        // Epilogue -> Qs / Ks / Vs (tf32-rounded; 8-col blocks never cross targets)
        #pragma unroll
        for (int nt = 0; nt < 6; nt++) {
            int c0 = wn * 48 + nt * 8;
            float* dst; int str, coff;
            if (c0 < 64)       { dst = Qs; str = 68; coff = c0; }
            else if (c0 < 128) { dst = Ks; str = 68; coff = c0 - 64; }
            else               { dst = Vs; str = 72; coff = c0 - 128; }
            #pragma unroll
            for (int mt = 0; mt < 2; mt++) {
                int row = m0 + wm * 32 + mt * 16 + g;
                float2 v0 = { ftf32(acc[mt][nt][0]), ftf32(acc[mt][nt][1]) };
                float2 v1 = { ftf32(acc[mt][nt][2]), ftf32(acc[mt][nt][3]) };
                *(float2*)(dst + row * str + coff + 2 * t)       = v0;
                *(float2*)(dst + (row + 8) * str + coff + 2 * t) = v1;
            }
        }
        __syncthreads();
    }

    // ================= causal attention, 4 query tiles =================
    #pragma unroll
    for (int qt = 0; qt < 4; qt++) {
        const int L   = (qt + 1) * 64;   // causal key range
        const int NTW = (qt + 1) * 2;    // 8-wide n-tiles per warp (round-robin)
        const int PST = L + 4;           // P row stride; P aliases consumed Q prefix
        float* Qt = Qs + qt * 64 * 68;
        float* Ps = Qs;

        // S = Q K^T  (warp m-tile 16 rows)
        float s[8][4];
        #pragma unroll
        for (int i = 0; i < 8; i++)
            #pragma unroll
            for (int j = 0; j < 4; j++) s[i][j] = 0.f;

        #pragma unroll
        for (int ks = 0; ks < 64; ks += 8) {
            const int rb = wm * 16;
            unsigned a[4] = {
                __float_as_uint(Qt[(rb + g    ) * 68 + ks + t    ]),
                __float_as_uint(Qt[(rb + g + 8) * 68 + ks + t    ]),
                __float_as_uint(Qt[(rb + g    ) * 68 + ks + t + 4]),
                __float_as_uint(Qt[(rb + g + 8) * 68 + ks + t + 4]) };
            #pragma unroll
            for (int i = 0; i < 8; i++) {
                if (i >= NTW) break;
                int col = (wn + 4 * i) * 8 + g;
                unsigned bb[2] = { __float_as_uint(Ks[col * 68 + ks + t    ]),
                                   __float_as_uint(Ks[col * 68 + ks + t + 4]) };
                mma_tf32(s[i], a, bb);
            }
        }

        // Causal mask + row max
        #pragma unroll
        for (int h = 0; h < 2; h++) {
            int row = wm * 16 + g + 8 * h;
            int qglob = qt * 64 + row;
            float mm = -1e30f;
            #pragma unroll
            for (int i = 0; i < 8; i++) {
                if (i >= NTW) break;
                int k0 = (wn + 4 * i) * 8 + 2 * t;
                float v0 = (k0     <= qglob) ? s[i][2 * h    ] : -1e30f;
                float v1 = (k0 + 1 <= qglob) ? s[i][2 * h + 1] : -1e30f;
                s[i][2 * h]     = v0;
                s[i][2 * h + 1] = v1;
                mm = fmaxf(mm, fmaxf(v0, v1));
            }
            mm = fmaxf(mm, __shfl_xor_sync(0xffffffffu, mm, 1));
            mm = fmaxf(mm, __shfl_xor_sync(0xffffffffu, mm, 2));
            if (t == 0) RM[row * 4 + wn] = mm;
        }
        __syncthreads();

        // exp + row sum
        #pragma unroll
        for (int h = 0; h < 2; h++) {
            int row = wm * 16 + g + 8 * h;
            float mf = fmaxf(fmaxf(RM[row * 4 + 0], RM[row * 4 + 1]),
                             fmaxf(RM[row * 4 + 2], RM[row * 4 + 3]));
            float ss = 0.f;
            #pragma unroll
            for (int i = 0; i < 8; i++) {
                if (i >= NTW) break;
                float p0 = __expf(s[i][2 * h]     - mf);
                float p1 = __expf(s[i][2 * h + 1] - mf);
                s[i][2 * h]     = p0;
                s[i][2 * h + 1] = p1;
                ss += p0 + p1;
            }
            ss += __shfl_xor_sync(0xffffffffu, ss, 1);
            ss += __shfl_xor_sync(0xffffffffu, ss, 2);
            if (t == 0) RL[row * 4 + wn] = ss;
        }
        __syncthreads();

        // normalize, tf32-round, write P (A-operand layout) over consumed Q
        #pragma unroll
        for (int h = 0; h < 2; h++) {
            int row = wm * 16 + g + 8 * h;
            float li = RL[row * 4 + 0] + RL[row * 4 + 1] + RL[row * 4 + 2] + RL[row * 4 + 3];
            float rinv = 1.0f / li;
            #pragma unroll
            for (int i = 0; i < 8; i++) {
                if (i >= NTW) break;
                int k0 = (wn + 4 * i) * 8 + 2 * t;
                float2 pv = { ftf32(s[i][2 * h] * rinv),
                              ftf32(s[i][2 * h + 1] * rinv) };
                *(float2*)(Ps + row * PST + k0) = pv;
            }
        }
        __syncthreads();

        // O = P @ V : warp tile 16(q) x 16(h)
        float o[2][4] = {};
        #pragma unroll 4
        for (int ks = 0; ks < L; ks += 8) {
            const int rb = wm * 16;
            unsigned a[4] = {
                __float_as_uint(Ps[(rb + g    ) * PST + ks + t    ]),
                __float_as_uint(Ps[(rb + g + 8) * PST + ks + t    ]),
                __float_as_uint(Ps[(rb + g    ) * PST + ks + t + 4]),
                __float_as_uint(Ps[(rb + g + 8) * PST + ks + t + 4]) };
            #pragma unroll
            for (int nt = 0; nt < 2; nt++) {
                int col = wn * 16 + nt * 8 + g;
                unsigned bb[2] = { __float_as_uint(Vs[(ks + t    ) * 72 + col]),
                                   __float_as_uint(Vs[(ks + t + 4) * 72 + col]) };
                mma_tf32(o[nt], a, bb);
            }
        }

        // Epilogue -> out [B*T, 64] fp32
        long r0 = bbase + qt * 64 + wm * 16 + g;
        #pragma unroll
        for (int nt = 0; nt < 2; nt++) {
            int cb = wn * 16 + nt * 8 + 2 * t;
            float2 v0 = { o[nt][0], o[nt][1] };
            float2 v1 = { o[nt][2], o[nt][3] };
            *(float2*)(out + r0 * kH + cb)       = v0;
            *(float2*)(out + (r0 + 8) * kH + cb) = v1;
        }
        __syncthreads();  // P region reused as next tile's P
    }
}

// ---------------- host launcher ----------------
extern "C" void kernel_launch(void* const* d_in, const int* in_sizes, int n_in,
                              void* d_out, int out_size) {
    const float* x  = (const float*)d_in[0];
    const float* Wq = (const float*)d_in[1];
    const float* Wk = (const float*)d_in[2];
    const float* Wv = (const float*)d_in[3];
    float* out = (float*)d_out;

    pack_w_kernel<<<(kC * kH + 255) / 256, 256>>>(Wq, Wk, Wv);

    cudaFuncSetAttribute(fused_kernel, cudaFuncAttributeMaxDynamicSharedMemorySize,
                         SMEM_FLOATS * (int)sizeof(float));
    fused_kernel<<<kB, 512, SMEM_FLOATS * sizeof(float)>>>(x, out);
}